// round 9
// baseline (speedup 1.0000x reference)
#include <cuda_runtime.h>

// ChamferLossSplit: B=256, N=M=256, D=4, PID_MAX=5.
// Inputs: target f32 [B,N,4], reco f32 [B,M,4], in_pid i32 [B,N], out_pid i32 [B,M]
// Output: f32[2] = (mean per_nonzero, mean per_zero)
//
// 512-thread CTA (16 warps), one batch per CTA, 2 CTAs resident per SM ->
// 8 warps/SMSP to hide latency. Warp w: rows-half h=w>>3 (128 rows, 4/lane),
// reco chunk c=w&7 (32 recos). R5-style shuffle ring: reco + its column-min
// travel the warp; after 32 steps the half-partial column min is home.
// Row mins combine over 8 chunk slabs; column mins over 2 half slabs.

#define NPTS 256
#define NTHREADS 512
#define RPL 4          // rows per lane
#define BIGC 1e18f     // sentinel coord for invalid points (4*BIGC^2 finite)
#define FULLMASK 0xffffffffu

__device__ __forceinline__ float warp_sum(float v) {
    #pragma unroll
    for (int o = 16; o; o >>= 1) v += __shfl_xor_sync(FULLMASK, v, o);
    return v;
}

__global__ void chamfer_init(float* out) {
    out[0] = 0.0f;
    out[1] = 0.0f;
}

__global__ __launch_bounds__(NTHREADS, 2) void chamfer_kernel(
    const float4* __restrict__ target,
    const float4* __restrict__ reco,
    const int* __restrict__ in_pid,
    const int* __restrict__ out_pid,
    float* __restrict__ out,
    float invB)
{
    __shared__ float s_row[8][NPTS];    // per-chunk partial row mins
    __shared__ float s_cminh[2][NPTS];  // per-half partial column mins
    __shared__ float s_red[6][8];       // cross-warp sum buffer

    const int b = blockIdx.x;
    const int i = threadIdx.x;
    const int lane = i & 31;
    const int wid  = i >> 5;          // 0..15
    const int c    = wid & 7;         // reco chunk
    const int h    = wid >> 3;        // rows half
    const float INF = __int_as_float(0x7f800000);
    const int base = b * NPTS;

    // ---- traveling reco for this lane: j = 32c + lane ----
    const int j0 = 32 * c + lane;
    const float4 r0 = reco[base + j0];
    const int my0 = (out_pid[base + j0] != 0);
    float4 rr = my0 ? r0 : make_float4(BIGC, BIGC, BIGC, BIGC);
    float rn = rr.x * rr.x;
    rn = fmaf(rr.y, rr.y, rn); rn = fmaf(rr.z, rr.z, rn); rn = fmaf(rr.w, rr.w, rn);

    // ---- load 4 rows per lane: row = 128h + lane + 32k ----
    float4 tv[RPL];
    float tn[RPL], rm[RPL];
    #pragma unroll
    for (int k = 0; k < RPL; k++) {
        const int row = 128 * h + lane + 32 * k;
        const float4 t0 = target[base + row];
        const int m = (in_pid[base + row] != 0);
        tv[k] = m ? t0 : make_float4(BIGC, BIGC, BIGC, BIGC);
        float a = tv[k].x * tv[k].x;
        a = fmaf(tv[k].y, tv[k].y, a);
        a = fmaf(tv[k].z, tv[k].z, a);
        a = fmaf(tv[k].w, tv[k].w, a);
        tn[k] = a;
        rm[k] = INF;
    }

    // ---- shuffle ring: 32 steps; reco + its column-min travel together ----
    float cmin = INF;
    const int src = (lane + 1) & 31;
    #pragma unroll 4
    for (int s = 0; s < 32; s++) {
        // prefetch next traveling reco (latency hidden under the math)
        const float nx = __shfl_sync(FULLMASK, rr.x, src);
        const float ny = __shfl_sync(FULLMASK, rr.y, src);
        const float nz = __shfl_sync(FULLMASK, rr.z, src);
        const float nw = __shfl_sync(FULLMASK, rr.w, src);
        const float nr = __shfl_sync(FULLMASK, rn,   src);

        float d2[RPL];
        #pragma unroll
        for (int k = 0; k < RPL; k++) {
            float dot = tv[k].x * rr.x;
            dot = fmaf(tv[k].y, rr.y, dot);
            dot = fmaf(tv[k].z, rr.z, dot);
            dot = fmaf(tv[k].w, rr.w, dot);
            d2[k] = fmaf(-2.0f, dot, tn[k]) + rn;
            rm[k] = fminf(rm[k], d2[k]);
        }
        const float m0 = fminf(d2[0], d2[1]);
        const float m1 = fminf(d2[2], d2[3]);
        cmin = fminf(cmin, fminf(m0, m1));
        cmin = __shfl_sync(FULLMASK, cmin, src);

        rr.x = nx; rr.y = ny; rr.z = nz; rr.w = nw; rn = nr;
    }
    // cmin: min over this half's 128 rows for column j0 (back home after 32 steps)

    s_cminh[h][j0] = cmin;
    #pragma unroll
    for (int k = 0; k < RPL; k++)
        s_row[c][128 * h + lane + 32 * k] = rm[k];
    __syncthreads();

    // ---- epilogue on first 256 threads: one point each ----
    if (i < NPTS) {
        float rowm = s_row[0][i];
        #pragma unroll
        for (int w = 1; w < 8; w++) rowm = fminf(rowm, s_row[w][i]);
        const float colm = fminf(s_cminh[0][i], s_cminh[1][i]);

        const float4 t0 = target[base + i];
        const float4 q0 = reco[base + i];
        const int mx = (in_pid[base + i] != 0);
        const int my = (out_pid[base + i] != 0);

        float a = t0.x * t0.x;
        a = fmaf(t0.y, t0.y, a); a = fmaf(t0.z, t0.z, a); a = fmaf(t0.w, t0.w, a);
        float cc = q0.x * q0.x;
        cc = fmaf(q0.y, q0.y, cc); cc = fmaf(q0.z, q0.z, cc); cc = fmaf(q0.w, q0.w, cc);

        float v[6];
        v[0] = mx ? 1.0f : 0.0f;                          // sum fx
        v[1] = my ? 1.0f : 0.0f;                          // sum fy
        v[2] = mx ? sqrtf(fmaxf(rowm, 0.0f)) : 0.0f;      // sum_xy
        v[3] = my ? sqrtf(fmaxf(colm, 0.0f)) : 0.0f;      // sum_yx
        v[4] = mx ? sqrtf(a) : 0.0f;                      // fallback sum ||x||
        v[5] = my ? 0.0f : sqrtf(cc);                     // sum ||y|| zero-pid

        #pragma unroll
        for (int k = 0; k < 6; k++) {
            const float ws = warp_sum(v[k]);
            if (lane == 0) s_red[k][wid] = ws;
        }
    }
    __syncthreads();

    if (i == 0) {
        float s[6];
        #pragma unroll
        for (int k = 0; k < 6; k++) {
            float acc = 0.0f;
            #pragma unroll
            for (int w = 0; w < 8; w++) acc += s_red[k][w];
            s[k] = acc;
        }
        const float sum_fx = s[0], sum_fy = s[1];
        const float sum_xy = s[2], sum_yx = s[3];
        const float sum_fb = s[4], sum_z  = s[5];

        const float n_in  = fmaxf(1.0f, sum_fx);
        const float n_out = fmaxf(1.0f, sum_fy);

        float per_nonzero;
        if (sum_fy == 0.0f) {
            per_nonzero = sum_fb / n_in;              // no valid reco
        } else if (sum_fx == 0.0f) {
            per_nonzero = 0.0f;                        // no valid target
        } else {
            per_nonzero = 0.5f * (sum_xy / n_out + sum_yx / n_in);
        }
        const float per_zero = sum_z / fmaxf(1.0f, (float)NPTS - sum_fy);

        atomicAdd(&out[0], per_nonzero * invB);
        atomicAdd(&out[1], per_zero * invB);
    }
}

extern "C" void kernel_launch(void* const* d_in, const int* in_sizes, int n_in,
                              void* d_out, int out_size)
{
    const float4* target  = (const float4*)d_in[0];
    const float4* reco    = (const float4*)d_in[1];
    const int*    in_pid  = (const int*)d_in[2];
    const int*    out_pid = (const int*)d_in[3];
    float*        out     = (float*)d_out;

    const int B = in_sizes[2] / NPTS;

    chamfer_init<<<1, 1>>>(out);
    chamfer_kernel<<<B, NTHREADS>>>(target, reco, in_pid, out_pid, out, 1.0f / (float)B);
}

// round 12
// speedup vs baseline: 1.0691x; 1.0691x over previous
#include <cuda_runtime.h>

// ChamferLossSplit: B=256, N=M=256, D=4, PID_MAX=5.
// Inputs: target f32 [B,N,4], reco f32 [B,M,4], in_pid i32 [B,N], out_pid i32 [B,M]
// Output: f32[2] = (mean per_nonzero, mean per_zero)
//
// R5 shuffle-ring layout (256 thr, 8 warps, lane holds 8 rows, warp owns 32
// recos that circulate with their column-min). R10 changes: traveling reco is
// pre-scaled s=-2r (saves the per-pair mul), masking via tn/rn=+INF (exact,
// no sentinel-coordinate cancellation), and single-kernel output via a
// last-block device-scratch reduction (no init launch).

#define NPTS 256
#define NWARP 8
#define RPL 8          // rows per lane
#define FULLMASK 0xffffffffu

__device__ float    g_scr0 = 0.0f, g_scr1 = 0.0f;
__device__ unsigned g_cnt = 0;

__device__ __forceinline__ float warp_sum(float v) {
    #pragma unroll
    for (int o = 16; o; o >>= 1) v += __shfl_xor_sync(FULLMASK, v, o);
    return v;
}

__global__ __launch_bounds__(NPTS) void chamfer_kernel(
    const float4* __restrict__ target,
    const float4* __restrict__ reco,
    const int* __restrict__ in_pid,
    const int* __restrict__ out_pid,
    float* __restrict__ out,
    float invB)
{
    __shared__ float s_row[NWARP * NPTS];   // per-warp partial row mins
    __shared__ float s_red[6][NWARP];       // cross-warp sum buffer

    const int b = blockIdx.x;
    const int i = threadIdx.x;
    const int lane = i & 31;
    const int wid  = i >> 5;
    const float INF = __int_as_float(0x7f800000);
    const int base = b * NPTS;

    // ---- own column j == i: load reco; travel s = -2*r and rn (INF if invalid) ----
    const float4 r0 = reco[base + i];
    const int my = (out_pid[base + i] != 0);
    float rn_real;
    {
        float c = r0.x * r0.x;
        c = fmaf(r0.y, r0.y, c); c = fmaf(r0.z, r0.z, c); c = fmaf(r0.w, r0.w, c);
        rn_real = c;
    }
    const float rn0_raw = sqrtf(rn_real);          // ||r0|| for zero-pid sum
    float sx = -2.0f * r0.x, sy = -2.0f * r0.y;
    float sz = -2.0f * r0.z, sw = -2.0f * r0.w;
    float rn = my ? rn_real : INF;

    // ---- load 8 rows per lane (rows lane+32k); k==wid is this thread's own row i ----
    float4 tv[RPL];
    float tn[RPL], rm[RPL];
    int   mx_self = 0;
    float t0n_self = 0.0f;
    #pragma unroll
    for (int k = 0; k < RPL; k++) {
        const int row = lane + 32 * k;
        const float4 t0 = target[base + row];
        const int m = (in_pid[base + row] != 0);
        tv[k] = t0;
        float a = t0.x * t0.x;
        a = fmaf(t0.y, t0.y, a);
        a = fmaf(t0.z, t0.z, a);
        a = fmaf(t0.w, t0.w, a);
        if (k == wid) {  // row == i
            mx_self = m;
            t0n_self = sqrtf(a);
        }
        tn[k] = m ? a : INF;   // invalid row -> all its pair d2 = +INF
        rm[k] = INF;
    }

    // ---- shuffle ring: 32 steps; scaled reco + its column-min travel together ----
    float cmin = INF;
    const int src = (lane + 1) & 31;
    #pragma unroll 4
    for (int s = 0; s < 32; s++) {
        // prefetch next traveling reco (latency hidden under the math)
        const float nx = __shfl_sync(FULLMASK, sx, src);
        const float ny = __shfl_sync(FULLMASK, sy, src);
        const float nz = __shfl_sync(FULLMASK, sz, src);
        const float nw = __shfl_sync(FULLMASK, sw, src);
        const float nr = __shfl_sync(FULLMASK, rn, src);

        float d2[RPL];
        #pragma unroll
        for (int k = 0; k < RPL; k++) {
            float acc = fmaf(tv[k].w, sw, tn[k]);
            acc = fmaf(tv[k].z, sz, acc);
            acc = fmaf(tv[k].y, sy, acc);
            acc = fmaf(tv[k].x, sx, acc);
            d2[k] = acc + rn;                 // tn + rn - 2*dot
            rm[k] = fminf(rm[k], d2[k]);
        }
        const float m0 = fminf(d2[0], d2[1]);
        const float m1 = fminf(d2[2], d2[3]);
        const float m2 = fminf(d2[4], d2[5]);
        const float m3 = fminf(d2[6], d2[7]);
        cmin = fminf(cmin, fminf(fminf(m0, m1), fminf(m2, m3)));
        cmin = __shfl_sync(FULLMASK, cmin, src);

        sx = nx; sy = ny; sz = nz; sw = nw; rn = nr;
    }
    // cmin is now the full column min for column i.

    // ---- combine per-warp partial row mins via smem slabs ----
    #pragma unroll
    for (int k = 0; k < RPL; k++)
        s_row[wid * NPTS + lane + 32 * k] = rm[k];
    __syncthreads();

    float rowm = s_row[i];
    #pragma unroll
    for (int w = 1; w < NWARP; w++) rowm = fminf(rowm, s_row[w * NPTS + i]);

    // ---- per-thread contributions (sqrt clamped: dot-trick can round <0) ----
    float v[6];
    v[0] = mx_self ? 1.0f : 0.0f;                              // sum fx
    v[1] = my ? 1.0f : 0.0f;                                   // sum fy
    v[2] = mx_self ? sqrtf(fmaxf(rowm, 0.0f)) : 0.0f;          // sum_xy
    v[3] = my ? sqrtf(fmaxf(cmin, 0.0f)) : 0.0f;               // sum_yx
    v[4] = mx_self ? t0n_self : 0.0f;                          // fallback sum ||x||
    v[5] = my ? 0.0f : rn0_raw;                                // sum ||y|| zero-pid

    #pragma unroll
    for (int k = 0; k < 6; k++) {
        const float ws = warp_sum(v[k]);
        if (lane == 0) s_red[k][wid] = ws;
    }
    __syncthreads();

    if (i == 0) {
        float s[6];
        #pragma unroll
        for (int k = 0; k < 6; k++) {
            float acc = 0.0f;
            #pragma unroll
            for (int w = 0; w < NWARP; w++) acc += s_red[k][w];
            s[k] = acc;
        }
        const float sum_fx = s[0], sum_fy = s[1];
        const float sum_xy = s[2], sum_yx = s[3];
        const float sum_fb = s[4], sum_z  = s[5];

        const float n_in  = fmaxf(1.0f, sum_fx);
        const float n_out = fmaxf(1.0f, sum_fy);

        float per_nonzero;
        if (sum_fy == 0.0f) {
            per_nonzero = sum_fb / n_in;              // no valid reco
        } else if (sum_fx == 0.0f) {
            per_nonzero = 0.0f;                        // no valid target
        } else {
            per_nonzero = 0.5f * (sum_xy / n_out + sum_yx / n_in);
        }
        const float per_zero = sum_z / fmaxf(1.0f, (float)NPTS - sum_fy);

        // last-block reduction: accumulate in device scratch, winner writes
        // d_out and re-zeros scratch so the next graph replay starts clean.
        atomicAdd(&g_scr0, per_nonzero * invB);
        atomicAdd(&g_scr1, per_zero * invB);
        __threadfence();
        const unsigned old = atomicAdd(&g_cnt, 1u);
        if (old == gridDim.x - 1) {
            __threadfence();
            volatile float* vs0 = &g_scr0;
            volatile float* vs1 = &g_scr1;
            const float o0 = *vs0;
            const float o1 = *vs1;
            out[0] = o0;
            out[1] = o1;
            *vs0 = 0.0f;
            *vs1 = 0.0f;
            __threadfence();
            g_cnt = 0;
        }
    }
}

extern "C" void kernel_launch(void* const* d_in, const int* in_sizes, int n_in,
                              void* d_out, int out_size)
{
    const float4* target  = (const float4*)d_in[0];
    const float4* reco    = (const float4*)d_in[1];
    const int*    in_pid  = (const int*)d_in[2];
    const int*    out_pid = (const int*)d_in[3];
    float*        out     = (float*)d_out;

    const int B = in_sizes[2] / NPTS;

    chamfer_kernel<<<B, NPTS>>>(target, reco, in_pid, out_pid, out, 1.0f / (float)B);
}